// round 13
// baseline (speedup 1.0000x reference)
#include <cuda_runtime.h>
#include <cuda_fp16.h>
#include <math.h>
#include <stdint.h>

#define NMAX 100000
#define EMAX 1000000
#define SAPAD 132

// ---------------- half2 <-> u32 bit casts ----------------
__device__ __forceinline__ uint32_t h2_bits(__half2 h) {
    return *reinterpret_cast<uint32_t*>(&h);
}
__device__ __forceinline__ __half2 bits_h2(uint32_t u) {
    return *reinterpret_cast<__half2*>(&u);
}

// ---------------- scratch (static device globals) ----------------
__device__ uint4  g_h0[(size_t)NMAX * 8];
__device__ uint4  g_hA[(size_t)NMAX * 8];
__device__ uint4  g_hB[(size_t)NMAX * 8];
__device__ uint4  g_hC[(size_t)NMAX * 8];
__device__ float4 g_f32out[(size_t)NMAX * 16];
__device__ float4 g_hlast_scratch[(size_t)NMAX * 32];
__device__ int    g_deg_out[NMAX];
__device__ int    g_deg_in[NMAX];
__device__ float  g_snorm[NMAX];
__device__ float  g_dnorm[NMAX];
__device__ int    g_rowptr[NMAX + 1];
__device__ int    g_cursor[NMAX];
__device__ int    g_partials[128];
__device__ int    g_dhist[256];
__device__ int    g_dcur[256];
__device__ int    g_perm[NMAX];
__device__ int2   g_edges[EMAX];   // .x = src, .y = bits of 0.9*snorm[src]*dnorm[dst]
__device__ unsigned int g_bar;     // grid barrier counter (reset each replay by k_zero_deg)

// ---------------- graph preprocessing ----------------
__global__ void k_zero_deg(int n) {
    int i = blockIdx.x * blockDim.x + threadIdx.x;
    if (i < n) { g_deg_out[i] = 0; g_deg_in[i] = 0; }
    if (i < 256) g_dhist[i] = 0;
    if (blockIdx.x == 0 && threadIdx.x == 0) g_bar = 0;
}

__global__ void k_degrees(const int* __restrict__ src, const int* __restrict__ dst, int e) {
    int i = blockIdx.x * blockDim.x + threadIdx.x;
    if (i < e) {
        atomicAdd(&g_deg_out[src[i]], 1);
        atomicAdd(&g_deg_in[dst[i]], 1);
    }
}

__global__ void k_norms_tilesum(int n) {
    int idx = blockIdx.x * 1024 + threadIdx.x;
    int din = 0;
    if (idx < n) {
        int dout = g_deg_out[idx];
        g_snorm[idx] = (dout > 0) ? rsqrtf((float)dout) : 0.f;
        din = g_deg_in[idx];
        g_dnorm[idx] = (din > 0) ? rsqrtf((float)din) : 0.f;
        atomicAdd(&g_dhist[min(din, 255)], 1);
    }
    int v = din;
    #pragma unroll
    for (int o = 16; o; o >>= 1) v += __shfl_down_sync(0xffffffffu, v, o);
    __shared__ int sm[32];
    if ((threadIdx.x & 31) == 0) sm[threadIdx.x >> 5] = v;
    __syncthreads();
    if (threadIdx.x < 32) {
        int s = sm[threadIdx.x];
        #pragma unroll
        for (int o = 16; o; o >>= 1) s += __shfl_down_sync(0xffffffffu, s, o);
        if (threadIdx.x == 0) g_partials[blockIdx.x] = s;
    }
}

__global__ void k_scan_partials(int ntiles) {
    int t = threadIdx.x;
    int v = (t < ntiles) ? g_partials[t] : 0;
    int lane = t & 31, w = t >> 5;
    int x = v;
    #pragma unroll
    for (int o = 1; o < 32; o <<= 1) {
        int y = __shfl_up_sync(0xffffffffu, x, o);
        if (lane >= o) x += y;
    }
    __shared__ int ws[4];
    if (lane == 31) ws[w] = x;
    __syncthreads();
    if (t == 0) {
        int a = 0;
        #pragma unroll
        for (int i = 0; i < 4; i++) { int tmp = ws[i]; ws[i] = a; a += tmp; }
    }
    __syncthreads();
    int excl = x - v + ws[w];
    if (t < ntiles) g_partials[t] = excl;
}

__global__ void k_apply_scan(int n) {
    int tile = blockIdx.x;
    int t = threadIdx.x;
    int idx = tile * 1024 + t;
    int v = (idx < n) ? g_deg_in[idx] : 0;
    int lane = t & 31, w = t >> 5;
    int x = v;
    #pragma unroll
    for (int o = 1; o < 32; o <<= 1) {
        int y = __shfl_up_sync(0xffffffffu, x, o);
        if (lane >= o) x += y;
    }
    __shared__ int ws[32];
    if (lane == 31) ws[w] = x;
    __syncthreads();
    if (t < 32) {
        int y = ws[t];
        #pragma unroll
        for (int o = 1; o < 32; o <<= 1) {
            int z = __shfl_up_sync(0xffffffffu, y, o);
            if (lane >= o) y += z;
        }
        ws[t] = y;
    }
    __syncthreads();
    int winc = (w > 0) ? ws[w - 1] : 0;
    int inc = x + winc + g_partials[tile];
    if (idx < n) {
        g_rowptr[idx + 1] = inc;
        g_cursor[idx] = inc - v;
    }
    if (idx == 0) g_rowptr[0] = 0;
}

__global__ void k_hist_scan() {
    int t = threadIdx.x;
    int v = g_dhist[t];
    int lane = t & 31, w = t >> 5;
    int x = v;
    #pragma unroll
    for (int o = 1; o < 32; o <<= 1) {
        int y = __shfl_up_sync(0xffffffffu, x, o);
        if (lane >= o) x += y;
    }
    __shared__ int ws[8];
    if (lane == 31) ws[w] = x;
    __syncthreads();
    if (t == 0) {
        int a = 0;
        #pragma unroll
        for (int i = 0; i < 8; i++) { int tmp = ws[i]; ws[i] = a; a += tmp; }
    }
    __syncthreads();
    g_dcur[t] = x - v + ws[w];
}

__global__ void k_perm(int n) {
    int i = blockIdx.x * blockDim.x + threadIdx.x;
    if (i < n) {
        int d = min(g_deg_in[i], 255);
        int pos = atomicAdd(&g_dcur[d], 1);
        g_perm[pos] = i;
    }
}

__global__ void k_fill(const int* __restrict__ src, const int* __restrict__ dst, int e) {
    int i = blockIdx.x * blockDim.x + threadIdx.x;
    if (i < e) {
        int d = dst[i];
        int s = src[i];
        int p = atomicAdd(&g_cursor[d], 1);
        int2 v;
        v.x = s;
        v.y = __float_as_int(0.9f * g_snorm[s] * g_dnorm[d]);
        g_edges[p] = v;
    }
}

// ---------------- persistent fused propagation ----------------
// grid barrier: fence+atomic arrive, volatile spin + fence acquire. All blocks
// co-resident (grid = SMs*5, launch_bounds(256,5), no smem) => no deadlock.
__device__ __forceinline__ void grid_bar(unsigned int target) {
    __syncthreads();
    if (threadIdx.x == 0) {
        __threadfence();
        atomicAdd(&g_bar, 1u);
        while (*((volatile unsigned int*)&g_bar) < target) { __nanosleep(64); }
        __threadfence();
    }
    __syncthreads();
}

#define ACC8CG(W, V) { \
    float2 _t0 = __half22float2(bits_h2((V).x)); \
    float2 _t1 = __half22float2(bits_h2((V).y)); \
    float2 _t2 = __half22float2(bits_h2((V).z)); \
    float2 _t3 = __half22float2(bits_h2((V).w)); \
    a0 = fmaf(W, _t0.x, a0); a1 = fmaf(W, _t0.y, a1); \
    a2 = fmaf(W, _t1.x, a2); a3 = fmaf(W, _t1.y, a3); \
    a4 = fmaf(W, _t2.x, a4); a5 = fmaf(W, _t2.y, a5); \
    a6 = fmaf(W, _t3.x, a6); a7 = fmaf(W, _t3.y, a7); }

// one APPNP step; feature reads via __ldcg (L2-only: buffers are rewritten
// within this kernel and L1 is NOT flushed between steps)
template<bool OUT32>
__device__ __forceinline__ void prop_step(
        const uint4* __restrict__ fp, const uint4* __restrict__ f0,
        uint4* __restrict__ fn16, float4* __restrict__ fn32,
        int n, int lane, int idx0, int stride) {
    for (int i = idx0; i < n; i += stride) {
        int node = __ldg(&g_perm[i]);              // degree-sorted order
        int beg = __ldg(&g_rowptr[node]);
        int end = __ldg(&g_rowptr[node + 1]);

        float a0 = 0.f, a1 = 0.f, a2 = 0.f, a3 = 0.f;
        float a4 = 0.f, a5 = 0.f, a6 = 0.f, a7 = 0.f;

        int e = beg;
        for (; e + 4 <= end; e += 4) {
            int2 e0 = __ldg(&g_edges[e + 0]);
            int2 e1 = __ldg(&g_edges[e + 1]);
            int2 e2 = __ldg(&g_edges[e + 2]);
            int2 e3 = __ldg(&g_edges[e + 3]);
            uint4 v0 = __ldcg(&fp[(size_t)e0.x * 8 + lane]);
            uint4 v1 = __ldcg(&fp[(size_t)e1.x * 8 + lane]);
            uint4 v2 = __ldcg(&fp[(size_t)e2.x * 8 + lane]);
            uint4 v3 = __ldcg(&fp[(size_t)e3.x * 8 + lane]);
            float w0 = __int_as_float(e0.y), w1 = __int_as_float(e1.y);
            float w2 = __int_as_float(e2.y), w3 = __int_as_float(e3.y);
            ACC8CG(w0, v0); ACC8CG(w1, v1); ACC8CG(w2, v2); ACC8CG(w3, v3);
        }
        if (e + 2 <= end) {
            int2 e0 = __ldg(&g_edges[e + 0]);
            int2 e1 = __ldg(&g_edges[e + 1]);
            uint4 v0 = __ldcg(&fp[(size_t)e0.x * 8 + lane]);
            uint4 v1 = __ldcg(&fp[(size_t)e1.x * 8 + lane]);
            float w0 = __int_as_float(e0.y), w1 = __int_as_float(e1.y);
            ACC8CG(w0, v0); ACC8CG(w1, v1);
            e += 2;
        }
        if (e < end) {
            int2 ev = __ldg(&g_edges[e]);
            uint4 v = __ldcg(&fp[(size_t)ev.x * 8 + lane]);
            float w = __int_as_float(ev.y);
            ACC8CG(w, v);
        }

        // + 0.1 * f0
        {
            uint4 b = __ldcg(&f0[(size_t)node * 8 + lane]);
            float2 t0 = __half22float2(bits_h2(b.x));
            float2 t1 = __half22float2(bits_h2(b.y));
            float2 t2 = __half22float2(bits_h2(b.z));
            float2 t3 = __half22float2(bits_h2(b.w));
            a0 = fmaf(0.1f, t0.x, a0); a1 = fmaf(0.1f, t0.y, a1);
            a2 = fmaf(0.1f, t1.x, a2); a3 = fmaf(0.1f, t1.y, a3);
            a4 = fmaf(0.1f, t2.x, a4); a5 = fmaf(0.1f, t2.y, a5);
            a6 = fmaf(0.1f, t3.x, a6); a7 = fmaf(0.1f, t3.y, a7);
        }

        if (OUT32) {
            fn32[(size_t)node * 16 + lane * 2 + 0] = make_float4(a0, a1, a2, a3);
            fn32[(size_t)node * 16 + lane * 2 + 1] = make_float4(a4, a5, a6, a7);
        } else {
            uint4 o;
            o.x = h2_bits(__float22half2_rn(make_float2(a0, a1)));
            o.y = h2_bits(__float22half2_rn(make_float2(a2, a3)));
            o.z = h2_bits(__float22half2_rn(make_float2(a4, a5)));
            o.w = h2_bits(__float22half2_rn(make_float2(a6, a7)));
            fn16[(size_t)node * 8 + lane] = o;
        }
    }
}

__global__ void __launch_bounds__(256, 5) k_prop_all(
        const float4* __restrict__ in32, float4* __restrict__ f32out, int n) {
    int lane = threadIdx.x & 7;
    int idx0 = blockIdx.x * 32 + (threadIdx.x >> 3);
    int stride = gridDim.x * 32;
    unsigned int tgt = gridDim.x;

    // phase 0: fp32 -> fp16 convert into g_h0
    {
        int tid = blockIdx.x * 256 + threadIdx.x;
        int total = gridDim.x * 256;
        int nch = n * 8;
        for (int i = tid; i < nch; i += total) {
            float4 x = __ldg(&in32[2 * i]);
            float4 y = __ldg(&in32[2 * i + 1]);
            uint4 o;
            o.x = h2_bits(__float22half2_rn(make_float2(x.x, x.y)));
            o.y = h2_bits(__float22half2_rn(make_float2(x.z, x.w)));
            o.z = h2_bits(__float22half2_rn(make_float2(y.x, y.y)));
            o.w = h2_bits(__float22half2_rn(make_float2(y.z, y.w)));
            g_h0[i] = o;
        }
    }
    grid_bar(tgt); tgt += gridDim.x;

    // gnn1: f0 = g_h0; ping-pong hA/hB (s even -> hA, odd -> hB); ends in hB
    const uint4* f = g_h0;
    for (int s = 0; s < 10; s++) {
        uint4* o = (s & 1) ? g_hB : g_hA;
        prop_step<false>(f, g_h0, o, nullptr, n, lane, idx0, stride);
        grid_bar(tgt); tgt += gridDim.x;
        f = o;
    }
    // gnn2: f0 = hB; steps 0..8 ping-pong hA/hC; ends in hA
    for (int s = 0; s < 9; s++) {
        uint4* o = (s & 1) ? g_hC : g_hA;
        prop_step<false>(f, g_hB, o, nullptr, n, lane, idx0, stride);
        grid_bar(tgt); tgt += gridDim.x;
        f = o;
    }
    // final step (20th): write fp32 MLP input
    prop_step<true>(f, g_hB, nullptr, f32out, n, lane, idx0, stride);
}

// ---------------- fused tf32 MLP (unchanged) ----------------
__device__ __forceinline__ uint32_t f2tf32(float v) {
    uint32_t u;
    asm("cvt.rna.tf32.f32 %0, %1;" : "=r"(u) : "f"(v));
    return u;
}

template<int K, int NF>
__device__ __forceinline__ void mma_stage(
        const uint32_t* __restrict__ sA, const uint32_t* __restrict__ sW,
        int wm, int wn, int g, int tg, float (&acc)[2][8][4]) {
    #pragma unroll
    for (int kk = 0; kk < K; kk += 8) {
        uint32_t afr[2][4];
        #pragma unroll
        for (int mf = 0; mf < 2; mf++) {
            int mr = wm * 32 + mf * 16 + g;
            afr[mf][0] = sA[(kk + tg    ) * SAPAD + mr    ];
            afr[mf][1] = sA[(kk + tg    ) * SAPAD + mr + 8];
            afr[mf][2] = sA[(kk + tg + 4) * SAPAD + mr    ];
            afr[mf][3] = sA[(kk + tg + 4) * SAPAD + mr + 8];
        }
        #pragma unroll
        for (int nf = 0; nf < NF; nf++) {
            int nr = wn * NF * 8 + nf * 8 + g;
            uint32_t b0 = sW[(kk + tg    ) * SAPAD + nr];
            uint32_t b1 = sW[(kk + tg + 4) * SAPAD + nr];
            #pragma unroll
            for (int mf = 0; mf < 2; mf++) {
                asm volatile(
                    "mma.sync.aligned.m16n8k8.row.col.f32.tf32.tf32.f32 "
                    "{%0,%1,%2,%3}, {%4,%5,%6,%7}, {%8,%9}, {%0,%1,%2,%3};"
                    : "+f"(acc[mf][nf][0]), "+f"(acc[mf][nf][1]),
                      "+f"(acc[mf][nf][2]), "+f"(acc[mf][nf][3])
                    : "r"(afr[mf][0]), "r"(afr[mf][1]), "r"(afr[mf][2]), "r"(afr[mf][3]),
                      "r"(b0), "r"(b1));
            }
        }
    }
}

__device__ __forceinline__ void zero_acc(float (&acc)[2][8][4]) {
    #pragma unroll
    for (int i = 0; i < 2; i++)
        #pragma unroll
        for (int j = 0; j < 8; j++)
            #pragma unroll
            for (int r = 0; r < 4; r++) acc[i][j][r] = 0.f;
}

template<int NF, bool RELU, bool TO_SA, bool TO_GM>
__device__ __forceinline__ void store_acts(
        float (&acc)[2][8][4], const float* __restrict__ bias,
        uint32_t* __restrict__ sA, int wm, int wn, int g, int tg,
        float* __restrict__ gm_out, int gm_cols, int col_limit,
        int rowBase, int M) {
    #pragma unroll
    for (int mf = 0; mf < 2; mf++) {
        int r0 = wm * 32 + mf * 16 + g, r1 = r0 + 8;
        #pragma unroll
        for (int nf = 0; nf < NF; nf++) {
            int c0 = wn * NF * 8 + nf * 8 + tg * 2, c1 = c0 + 1;
            float bv0 = (c0 < col_limit) ? bias[c0] : 0.f;
            float bv1 = (c1 < col_limit) ? bias[c1] : 0.f;
            float v00 = acc[mf][nf][0] + bv0;
            float v01 = acc[mf][nf][1] + bv1;
            float v10 = acc[mf][nf][2] + bv0;
            float v11 = acc[mf][nf][3] + bv1;
            if (RELU) {
                v00 = fmaxf(v00, 0.f); v01 = fmaxf(v01, 0.f);
                v10 = fmaxf(v10, 0.f); v11 = fmaxf(v11, 0.f);
            }
            if (TO_SA) {
                sA[c0 * SAPAD + r0] = f2tf32(v00);
                sA[c1 * SAPAD + r0] = f2tf32(v01);
                sA[c0 * SAPAD + r1] = f2tf32(v10);
                sA[c1 * SAPAD + r1] = f2tf32(v11);
            }
            if (TO_GM) {
                int gr0 = rowBase + r0, gr1 = rowBase + r1;
                if (gr0 < M) {
                    if (c0 < col_limit) gm_out[(size_t)gr0 * gm_cols + c0] = v00;
                    if (c1 < col_limit) gm_out[(size_t)gr0 * gm_cols + c1] = v01;
                }
                if (gr1 < M) {
                    if (c0 < col_limit) gm_out[(size_t)gr1 * gm_cols + c0] = v10;
                    if (c1 < col_limit) gm_out[(size_t)gr1 * gm_cols + c1] = v11;
                }
            }
        }
    }
}

__global__ void __launch_bounds__(256) k_mlp(
        const float* __restrict__ X,
        const float* __restrict__ W1,  const float* __restrict__ b1,
        const float* __restrict__ W2,  const float* __restrict__ b2,
        const float* __restrict__ Wh1, const float* __restrict__ bh1,
        const float* __restrict__ Wh2, const float* __restrict__ bh2,
        float* __restrict__ hlast, float* __restrict__ out, int M) {
    extern __shared__ uint32_t sh[];
    uint32_t* sA = sh;
    uint32_t* sW = sh + 128 * SAPAD;

    int tid = threadIdx.x;
    int wid = tid >> 5, lane = tid & 31;
    int g = lane >> 2, tg = lane & 3;
    int wm = wid & 3, wn = wid >> 2;
    int rowBase = blockIdx.x * 128;

    #pragma unroll
    for (int i = tid; i < 128 * 16; i += 256) {
        int m = i / 16, kq = i % 16;
        float4 v = make_float4(0.f, 0.f, 0.f, 0.f);
        int gm = rowBase + m;
        if (gm < M) v = *reinterpret_cast<const float4*>(&X[(size_t)gm * 64 + kq * 4]);
        sA[(kq * 4 + 0) * SAPAD + m] = f2tf32(v.x);
        sA[(kq * 4 + 1) * SAPAD + m] = f2tf32(v.y);
        sA[(kq * 4 + 2) * SAPAD + m] = f2tf32(v.z);
        sA[(kq * 4 + 3) * SAPAD + m] = f2tf32(v.w);
    }
    #pragma unroll
    for (int i = tid; i < 64 * 32; i += 256) {
        int k = i / 32, nq = i % 32;
        float4 v = *reinterpret_cast<const float4*>(&W1[(size_t)k * 128 + nq * 4]);
        sW[k * SAPAD + nq * 4 + 0] = f2tf32(v.x);
        sW[k * SAPAD + nq * 4 + 1] = f2tf32(v.y);
        sW[k * SAPAD + nq * 4 + 2] = f2tf32(v.z);
        sW[k * SAPAD + nq * 4 + 3] = f2tf32(v.w);
    }
    __syncthreads();

    float acc[2][8][4];

    zero_acc(acc);
    mma_stage<64, 8>(sA, sW, wm, wn, g, tg, acc);
    __syncthreads();
    store_acts<8, true, true, false>(acc, b1, sA, wm, wn, g, tg, nullptr, 0, 128, rowBase, M);
    #pragma unroll
    for (int i = tid; i < 128 * 32; i += 256) {
        int k = i / 32, nq = i % 32;
        float4 v = *reinterpret_cast<const float4*>(&W2[(size_t)k * 128 + nq * 4]);
        sW[k * SAPAD + nq * 4 + 0] = f2tf32(v.x);
        sW[k * SAPAD + nq * 4 + 1] = f2tf32(v.y);
        sW[k * SAPAD + nq * 4 + 2] = f2tf32(v.z);
        sW[k * SAPAD + nq * 4 + 3] = f2tf32(v.w);
    }
    __syncthreads();

    zero_acc(acc);
    mma_stage<128, 8>(sA, sW, wm, wn, g, tg, acc);
    __syncthreads();
    store_acts<8, false, true, true>(acc, b2, sA, wm, wn, g, tg, hlast, 128, 128, rowBase, M);
    #pragma unroll
    for (int i = tid; i < 128 * 16; i += 256) {
        int k = i / 16, nq = i % 16;
        float4 v = *reinterpret_cast<const float4*>(&Wh1[(size_t)k * 64 + nq * 4]);
        sW[k * SAPAD + nq * 4 + 0] = f2tf32(v.x);
        sW[k * SAPAD + nq * 4 + 1] = f2tf32(v.y);
        sW[k * SAPAD + nq * 4 + 2] = f2tf32(v.z);
        sW[k * SAPAD + nq * 4 + 3] = f2tf32(v.w);
    }
    __syncthreads();

    zero_acc(acc);
    mma_stage<128, 4>(sA, sW, wm, wn, g, tg, acc);
    __syncthreads();
    store_acts<4, true, true, false>(acc, bh1, sA, wm, wn, g, tg, nullptr, 0, 64, rowBase, M);
    #pragma unroll
    for (int i = tid; i < 64 * 64; i += 256) {
        int k = i / 64, j = i % 64;
        float v = (j < 40) ? Wh2[(size_t)k * 40 + j] : 0.f;
        sW[k * SAPAD + j] = f2tf32(v);
    }
    __syncthreads();

    zero_acc(acc);
    mma_stage<64, 4>(sA, sW, wm, wn, g, tg, acc);
    __syncthreads();
    store_acts<4, false, false, true>(acc, bh2, nullptr, wm, wn, g, tg, out, 40, 40, rowBase, M);
}

// ---------------- launch ----------------
extern "C" void kernel_launch(void* const* d_in, const int* in_sizes, int n_in,
                              void* d_out, int out_size) {
    const float* input_feat = (const float*)d_in[0];
    const int*   src = (const int*)d_in[1];
    const int*   dst = (const int*)d_in[2];
    const float* W1  = (const float*)d_in[3];
    const float* b1  = (const float*)d_in[4];
    const float* W2  = (const float*)d_in[5];
    const float* b2  = (const float*)d_in[6];
    const float* Wh1 = (const float*)d_in[7];
    const float* bh1 = (const float*)d_in[8];
    const float* Wh2 = (const float*)d_in[9];
    const float* bh2 = (const float*)d_in[10];

    int n = in_sizes[0] / 64;
    int e = in_sizes[1];
    if (n > NMAX) n = NMAX;
    if (e > EMAX) e = EMAX;

    float* outp = (float*)d_out;

    float4 *f32out, *hl_scratch;
    cudaGetSymbolAddress((void**)&f32out, g_f32out);
    cudaGetSymbolAddress((void**)&hl_scratch, g_hlast_scratch);

    float* hlast = (out_size >= n * 168) ? (outp + (size_t)n * 40) : (float*)hl_scratch;

    int nb = (n + 255) / 256;
    int eb = (e + 255) / 256;
    int ntiles = (n + 1023) / 1024;

    k_zero_deg<<<nb, 256>>>(n);
    k_degrees<<<eb, 256>>>(src, dst, e);
    k_norms_tilesum<<<ntiles, 1024>>>(n);
    k_scan_partials<<<1, 128>>>(ntiles);
    k_apply_scan<<<ntiles, 1024>>>(n);
    k_hist_scan<<<1, 256>>>();
    k_perm<<<nb, 256>>>(n);
    k_fill<<<eb, 256>>>(src, dst, e);

    // persistent fused propagation: convert + 20 steps, one kernel
    int dev = 0, smCount = 148;
    cudaGetDevice(&dev);
    cudaDeviceGetAttribute(&smCount, cudaDevAttrMultiProcessorCount, dev);
    int pb = smCount * 5;   // all blocks co-resident (launch_bounds(256,5), no smem)
    k_prop_all<<<pb, 256>>>((const float4*)input_feat, f32out, n);

    // fused MLP (fp32 input, unchanged)
    const int MLP_SMEM = 2 * 128 * SAPAD * 4;
    cudaFuncSetAttribute(k_mlp, cudaFuncAttributeMaxDynamicSharedMemorySize, MLP_SMEM);
    int gridM = (n + 127) / 128;
    k_mlp<<<gridM, 256, MLP_SMEM>>>((const float*)f32out, W1, b1, W2, b2,
                                    Wh1, bh1, Wh2, bh2, hlast, outp, n);
}

// round 14
// speedup vs baseline: 1.0617x; 1.0617x over previous
#include <cuda_runtime.h>
#include <cuda_fp16.h>
#include <math.h>
#include <stdint.h>

#define NMAX 100000
#define EMAX 1000000
#define SAPAD 132

// ---------------- half2 <-> u32 bit casts ----------------
__device__ __forceinline__ uint32_t h2_bits(__half2 h) {
    return *reinterpret_cast<uint32_t*>(&h);
}
__device__ __forceinline__ __half2 bits_h2(uint32_t u) {
    return *reinterpret_cast<__half2*>(&u);
}

// ---------------- scratch (static device globals) ----------------
__device__ uint4  g_h0[(size_t)NMAX * 8];
__device__ uint4  g_hA[(size_t)NMAX * 8];
__device__ uint4  g_hB[(size_t)NMAX * 8];
__device__ uint4  g_hC[(size_t)NMAX * 8];
__device__ float4 g_f32out[(size_t)NMAX * 16];
__device__ float4 g_hlast_scratch[(size_t)NMAX * 32];
__device__ int    g_deg_out[NMAX];
__device__ int    g_deg_in[NMAX];
__device__ float  g_snorm[NMAX];
__device__ float  g_dnorm[NMAX];
__device__ int    g_rowptr[NMAX + 1];
__device__ int    g_cursor[NMAX];
__device__ int    g_partials[128];
__device__ int    g_dhist[256];
__device__ int    g_dcur[256];
__device__ int    g_perm[NMAX];
__device__ int2   g_edges[EMAX];   // .x = src, .y = bits of 0.9*snorm[src]*dnorm[dst]

// ---------------- graph preprocessing ----------------
__global__ void k_zero_deg(int n) {
    int i = blockIdx.x * blockDim.x + threadIdx.x;
    if (i < n) { g_deg_out[i] = 0; g_deg_in[i] = 0; }
    if (i < 256) g_dhist[i] = 0;
}

__global__ void k_degrees(const int* __restrict__ src, const int* __restrict__ dst, int e) {
    int i = blockIdx.x * blockDim.x + threadIdx.x;
    if (i < e) {
        atomicAdd(&g_deg_out[src[i]], 1);
        atomicAdd(&g_deg_in[dst[i]], 1);
    }
}

__global__ void k_norms_tilesum(int n) {
    int idx = blockIdx.x * 1024 + threadIdx.x;
    int din = 0;
    if (idx < n) {
        int dout = g_deg_out[idx];
        g_snorm[idx] = (dout > 0) ? rsqrtf((float)dout) : 0.f;
        din = g_deg_in[idx];
        g_dnorm[idx] = (din > 0) ? rsqrtf((float)din) : 0.f;
        atomicAdd(&g_dhist[min(din, 255)], 1);     // degree histogram for counting sort
    }
    int v = din;
    #pragma unroll
    for (int o = 16; o; o >>= 1) v += __shfl_down_sync(0xffffffffu, v, o);
    __shared__ int sm[32];
    if ((threadIdx.x & 31) == 0) sm[threadIdx.x >> 5] = v;
    __syncthreads();
    if (threadIdx.x < 32) {
        int s = sm[threadIdx.x];
        #pragma unroll
        for (int o = 16; o; o >>= 1) s += __shfl_down_sync(0xffffffffu, s, o);
        if (threadIdx.x == 0) g_partials[blockIdx.x] = s;
    }
}

__global__ void k_scan_partials(int ntiles) {
    int t = threadIdx.x;
    int v = (t < ntiles) ? g_partials[t] : 0;
    int lane = t & 31, w = t >> 5;
    int x = v;
    #pragma unroll
    for (int o = 1; o < 32; o <<= 1) {
        int y = __shfl_up_sync(0xffffffffu, x, o);
        if (lane >= o) x += y;
    }
    __shared__ int ws[4];
    if (lane == 31) ws[w] = x;
    __syncthreads();
    if (t == 0) {
        int a = 0;
        #pragma unroll
        for (int i = 0; i < 4; i++) { int tmp = ws[i]; ws[i] = a; a += tmp; }
    }
    __syncthreads();
    int excl = x - v + ws[w];
    if (t < ntiles) g_partials[t] = excl;
}

__global__ void k_apply_scan(int n) {
    int tile = blockIdx.x;
    int t = threadIdx.x;
    int idx = tile * 1024 + t;
    int v = (idx < n) ? g_deg_in[idx] : 0;
    int lane = t & 31, w = t >> 5;
    int x = v;
    #pragma unroll
    for (int o = 1; o < 32; o <<= 1) {
        int y = __shfl_up_sync(0xffffffffu, x, o);
        if (lane >= o) x += y;
    }
    __shared__ int ws[32];
    if (lane == 31) ws[w] = x;
    __syncthreads();
    if (t < 32) {
        int y = ws[t];
        #pragma unroll
        for (int o = 1; o < 32; o <<= 1) {
            int z = __shfl_up_sync(0xffffffffu, y, o);
            if (lane >= o) y += z;
        }
        ws[t] = y;
    }
    __syncthreads();
    int winc = (w > 0) ? ws[w - 1] : 0;
    int inc = x + winc + g_partials[tile];
    if (idx < n) {
        g_rowptr[idx + 1] = inc;
        g_cursor[idx] = inc - v;
    }
    if (idx == 0) g_rowptr[0] = 0;
}

// exclusive scan of 256-entry degree histogram (single block, 256 threads)
__global__ void k_hist_scan() {
    int t = threadIdx.x;
    int v = g_dhist[t];
    int lane = t & 31, w = t >> 5;
    int x = v;
    #pragma unroll
    for (int o = 1; o < 32; o <<= 1) {
        int y = __shfl_up_sync(0xffffffffu, x, o);
        if (lane >= o) x += y;
    }
    __shared__ int ws[8];
    if (lane == 31) ws[w] = x;
    __syncthreads();
    if (t == 0) {
        int a = 0;
        #pragma unroll
        for (int i = 0; i < 8; i++) { int tmp = ws[i]; ws[i] = a; a += tmp; }
    }
    __syncthreads();
    g_dcur[t] = x - v + ws[w];   // exclusive prefix = start cursor for degree t
}

// scatter node ids into degree-sorted permutation
__global__ void k_perm(int n) {
    int i = blockIdx.x * blockDim.x + threadIdx.x;
    if (i < n) {
        int d = min(g_deg_in[i], 255);
        int pos = atomicAdd(&g_dcur[d], 1);
        g_perm[pos] = i;
    }
}

__global__ void k_fill(const int* __restrict__ src, const int* __restrict__ dst, int e) {
    int i = blockIdx.x * blockDim.x + threadIdx.x;
    if (i < e) {
        int d = dst[i];
        int s = src[i];
        int p = atomicAdd(&g_cursor[d], 1);
        int2 v;
        v.x = s;
        v.y = __float_as_int(0.9f * g_snorm[s] * g_dnorm[d]);
        g_edges[p] = v;
    }
}

// fp32 features -> fp16 rows
__global__ void k_to_half(const float4* __restrict__ in, uint4* __restrict__ out, int nchunks) {
    int i = blockIdx.x * blockDim.x + threadIdx.x;
    if (i < nchunks) {
        float4 x = in[2 * i];
        float4 y = in[2 * i + 1];
        uint4 o;
        o.x = h2_bits(__float22half2_rn(make_float2(x.x, x.y)));
        o.y = h2_bits(__float22half2_rn(make_float2(x.z, x.w)));
        o.z = h2_bits(__float22half2_rn(make_float2(y.x, y.y)));
        o.w = h2_bits(__float22half2_rn(make_float2(y.z, y.w)));
        out[i] = o;
    }
}

// ---------------- APPNP propagation: fp16 rows, 8 lanes/node, degree-sorted order ----------------
#define ACC8(W, V) { \
    float2 _t0 = __half22float2(bits_h2((V).x)); \
    float2 _t1 = __half22float2(bits_h2((V).y)); \
    float2 _t2 = __half22float2(bits_h2((V).z)); \
    float2 _t3 = __half22float2(bits_h2((V).w)); \
    a0 = fmaf(W, _t0.x, a0); a1 = fmaf(W, _t0.y, a1); \
    a2 = fmaf(W, _t1.x, a2); a3 = fmaf(W, _t1.y, a3); \
    a4 = fmaf(W, _t2.x, a4); a5 = fmaf(W, _t2.y, a5); \
    a6 = fmaf(W, _t3.x, a6); a7 = fmaf(W, _t3.y, a7); }

template<bool OUT32>
__global__ void __launch_bounds__(256, 6) k_prop_h(
        const uint4* __restrict__ fp, const uint4* __restrict__ f0,
        void* __restrict__ fnv, int n) {
    int lane = threadIdx.x & 7;                    // 8 lanes per node
    int idx0 = blockIdx.x * 32 + (threadIdx.x >> 3);
    int stride = gridDim.x * 32;

    for (int i = idx0; i < n; i += stride) {
        int node = __ldg(&g_perm[i]);              // degree-sorted order
        int beg = __ldg(&g_rowptr[node]);
        int end = __ldg(&g_rowptr[node + 1]);

        float a0 = 0.f, a1 = 0.f, a2 = 0.f, a3 = 0.f;
        float a4 = 0.f, a5 = 0.f, a6 = 0.f, a7 = 0.f;

        int e = beg;
        for (; e + 4 <= end; e += 4) {
            int2 e0 = __ldg(&g_edges[e + 0]);
            int2 e1 = __ldg(&g_edges[e + 1]);
            int2 e2 = __ldg(&g_edges[e + 2]);
            int2 e3 = __ldg(&g_edges[e + 3]);
            uint4 v0 = __ldg(&fp[(size_t)e0.x * 8 + lane]);
            uint4 v1 = __ldg(&fp[(size_t)e1.x * 8 + lane]);
            uint4 v2 = __ldg(&fp[(size_t)e2.x * 8 + lane]);
            uint4 v3 = __ldg(&fp[(size_t)e3.x * 8 + lane]);
            float w0 = __int_as_float(e0.y), w1 = __int_as_float(e1.y);
            float w2 = __int_as_float(e2.y), w3 = __int_as_float(e3.y);
            ACC8(w0, v0); ACC8(w1, v1); ACC8(w2, v2); ACC8(w3, v3);
        }
        if (e + 2 <= end) {
            int2 e0 = __ldg(&g_edges[e + 0]);
            int2 e1 = __ldg(&g_edges[e + 1]);
            uint4 v0 = __ldg(&fp[(size_t)e0.x * 8 + lane]);
            uint4 v1 = __ldg(&fp[(size_t)e1.x * 8 + lane]);
            float w0 = __int_as_float(e0.y), w1 = __int_as_float(e1.y);
            ACC8(w0, v0); ACC8(w1, v1);
            e += 2;
        }
        if (e < end) {
            int2 ev = __ldg(&g_edges[e]);
            uint4 v = __ldg(&fp[(size_t)ev.x * 8 + lane]);
            float w = __int_as_float(ev.y);
            ACC8(w, v);
        }

        // + 0.1 * f0
        {
            uint4 b = __ldg(&f0[(size_t)node * 8 + lane]);
            float2 t0 = __half22float2(bits_h2(b.x));
            float2 t1 = __half22float2(bits_h2(b.y));
            float2 t2 = __half22float2(bits_h2(b.z));
            float2 t3 = __half22float2(bits_h2(b.w));
            a0 = fmaf(0.1f, t0.x, a0); a1 = fmaf(0.1f, t0.y, a1);
            a2 = fmaf(0.1f, t1.x, a2); a3 = fmaf(0.1f, t1.y, a3);
            a4 = fmaf(0.1f, t2.x, a4); a5 = fmaf(0.1f, t2.y, a5);
            a6 = fmaf(0.1f, t3.x, a6); a7 = fmaf(0.1f, t3.y, a7);
        }

        if (OUT32) {
            float4* out = (float4*)fnv;
            out[(size_t)node * 16 + lane * 2 + 0] = make_float4(a0, a1, a2, a3);
            out[(size_t)node * 16 + lane * 2 + 1] = make_float4(a4, a5, a6, a7);
        } else {
            uint4 o;
            o.x = h2_bits(__float22half2_rn(make_float2(a0, a1)));
            o.y = h2_bits(__float22half2_rn(make_float2(a2, a3)));
            o.z = h2_bits(__float22half2_rn(make_float2(a4, a5)));
            o.w = h2_bits(__float22half2_rn(make_float2(a6, a7)));
            ((uint4*)fnv)[(size_t)node * 8 + lane] = o;
        }
    }
}

// ---------------- fused tf32 MLP (unchanged) ----------------
__device__ __forceinline__ uint32_t f2tf32(float v) {
    uint32_t u;
    asm("cvt.rna.tf32.f32 %0, %1;" : "=r"(u) : "f"(v));
    return u;
}

template<int K, int NF>
__device__ __forceinline__ void mma_stage(
        const uint32_t* __restrict__ sA, const uint32_t* __restrict__ sW,
        int wm, int wn, int g, int tg, float (&acc)[2][8][4]) {
    #pragma unroll
    for (int kk = 0; kk < K; kk += 8) {
        uint32_t afr[2][4];
        #pragma unroll
        for (int mf = 0; mf < 2; mf++) {
            int mr = wm * 32 + mf * 16 + g;
            afr[mf][0] = sA[(kk + tg    ) * SAPAD + mr    ];
            afr[mf][1] = sA[(kk + tg    ) * SAPAD + mr + 8];
            afr[mf][2] = sA[(kk + tg + 4) * SAPAD + mr    ];
            afr[mf][3] = sA[(kk + tg + 4) * SAPAD + mr + 8];
        }
        #pragma unroll
        for (int nf = 0; nf < NF; nf++) {
            int nr = wn * NF * 8 + nf * 8 + g;
            uint32_t b0 = sW[(kk + tg    ) * SAPAD + nr];
            uint32_t b1 = sW[(kk + tg + 4) * SAPAD + nr];
            #pragma unroll
            for (int mf = 0; mf < 2; mf++) {
                asm volatile(
                    "mma.sync.aligned.m16n8k8.row.col.f32.tf32.tf32.f32 "
                    "{%0,%1,%2,%3}, {%4,%5,%6,%7}, {%8,%9}, {%0,%1,%2,%3};"
                    : "+f"(acc[mf][nf][0]), "+f"(acc[mf][nf][1]),
                      "+f"(acc[mf][nf][2]), "+f"(acc[mf][nf][3])
                    : "r"(afr[mf][0]), "r"(afr[mf][1]), "r"(afr[mf][2]), "r"(afr[mf][3]),
                      "r"(b0), "r"(b1));
            }
        }
    }
}

__device__ __forceinline__ void zero_acc(float (&acc)[2][8][4]) {
    #pragma unroll
    for (int i = 0; i < 2; i++)
        #pragma unroll
        for (int j = 0; j < 8; j++)
            #pragma unroll
            for (int r = 0; r < 4; r++) acc[i][j][r] = 0.f;
}

template<int NF, bool RELU, bool TO_SA, bool TO_GM>
__device__ __forceinline__ void store_acts(
        float (&acc)[2][8][4], const float* __restrict__ bias,
        uint32_t* __restrict__ sA, int wm, int wn, int g, int tg,
        float* __restrict__ gm_out, int gm_cols, int col_limit,
        int rowBase, int M) {
    #pragma unroll
    for (int mf = 0; mf < 2; mf++) {
        int r0 = wm * 32 + mf * 16 + g, r1 = r0 + 8;
        #pragma unroll
        for (int nf = 0; nf < NF; nf++) {
            int c0 = wn * NF * 8 + nf * 8 + tg * 2, c1 = c0 + 1;
            float bv0 = (c0 < col_limit) ? bias[c0] : 0.f;
            float bv1 = (c1 < col_limit) ? bias[c1] : 0.f;
            float v00 = acc[mf][nf][0] + bv0;
            float v01 = acc[mf][nf][1] + bv1;
            float v10 = acc[mf][nf][2] + bv0;
            float v11 = acc[mf][nf][3] + bv1;
            if (RELU) {
                v00 = fmaxf(v00, 0.f); v01 = fmaxf(v01, 0.f);
                v10 = fmaxf(v10, 0.f); v11 = fmaxf(v11, 0.f);
            }
            if (TO_SA) {
                sA[c0 * SAPAD + r0] = f2tf32(v00);
                sA[c1 * SAPAD + r0] = f2tf32(v01);
                sA[c0 * SAPAD + r1] = f2tf32(v10);
                sA[c1 * SAPAD + r1] = f2tf32(v11);
            }
            if (TO_GM) {
                int gr0 = rowBase + r0, gr1 = rowBase + r1;
                if (gr0 < M) {
                    if (c0 < col_limit) gm_out[(size_t)gr0 * gm_cols + c0] = v00;
                    if (c1 < col_limit) gm_out[(size_t)gr0 * gm_cols + c1] = v01;
                }
                if (gr1 < M) {
                    if (c0 < col_limit) gm_out[(size_t)gr1 * gm_cols + c0] = v10;
                    if (c1 < col_limit) gm_out[(size_t)gr1 * gm_cols + c1] = v11;
                }
            }
        }
    }
}

__global__ void __launch_bounds__(256) k_mlp(
        const float* __restrict__ X,
        const float* __restrict__ W1,  const float* __restrict__ b1,
        const float* __restrict__ W2,  const float* __restrict__ b2,
        const float* __restrict__ Wh1, const float* __restrict__ bh1,
        const float* __restrict__ Wh2, const float* __restrict__ bh2,
        float* __restrict__ hlast, float* __restrict__ out, int M) {
    extern __shared__ uint32_t sh[];
    uint32_t* sA = sh;
    uint32_t* sW = sh + 128 * SAPAD;

    int tid = threadIdx.x;
    int wid = tid >> 5, lane = tid & 31;
    int g = lane >> 2, tg = lane & 3;
    int wm = wid & 3, wn = wid >> 2;
    int rowBase = blockIdx.x * 128;

    #pragma unroll
    for (int i = tid; i < 128 * 16; i += 256) {
        int m = i / 16, kq = i % 16;
        float4 v = make_float4(0.f, 0.f, 0.f, 0.f);
        int gm = rowBase + m;
        if (gm < M) v = *reinterpret_cast<const float4*>(&X[(size_t)gm * 64 + kq * 4]);
        sA[(kq * 4 + 0) * SAPAD + m] = f2tf32(v.x);
        sA[(kq * 4 + 1) * SAPAD + m] = f2tf32(v.y);
        sA[(kq * 4 + 2) * SAPAD + m] = f2tf32(v.z);
        sA[(kq * 4 + 3) * SAPAD + m] = f2tf32(v.w);
    }
    #pragma unroll
    for (int i = tid; i < 64 * 32; i += 256) {
        int k = i / 32, nq = i % 32;
        float4 v = *reinterpret_cast<const float4*>(&W1[(size_t)k * 128 + nq * 4]);
        sW[k * SAPAD + nq * 4 + 0] = f2tf32(v.x);
        sW[k * SAPAD + nq * 4 + 1] = f2tf32(v.y);
        sW[k * SAPAD + nq * 4 + 2] = f2tf32(v.z);
        sW[k * SAPAD + nq * 4 + 3] = f2tf32(v.w);
    }
    __syncthreads();

    float acc[2][8][4];

    zero_acc(acc);
    mma_stage<64, 8>(sA, sW, wm, wn, g, tg, acc);
    __syncthreads();
    store_acts<8, true, true, false>(acc, b1, sA, wm, wn, g, tg, nullptr, 0, 128, rowBase, M);
    #pragma unroll
    for (int i = tid; i < 128 * 32; i += 256) {
        int k = i / 32, nq = i % 32;
        float4 v = *reinterpret_cast<const float4*>(&W2[(size_t)k * 128 + nq * 4]);
        sW[k * SAPAD + nq * 4 + 0] = f2tf32(v.x);
        sW[k * SAPAD + nq * 4 + 1] = f2tf32(v.y);
        sW[k * SAPAD + nq * 4 + 2] = f2tf32(v.z);
        sW[k * SAPAD + nq * 4 + 3] = f2tf32(v.w);
    }
    __syncthreads();

    zero_acc(acc);
    mma_stage<128, 8>(sA, sW, wm, wn, g, tg, acc);
    __syncthreads();
    store_acts<8, false, true, true>(acc, b2, sA, wm, wn, g, tg, hlast, 128, 128, rowBase, M);
    #pragma unroll
    for (int i = tid; i < 128 * 16; i += 256) {
        int k = i / 16, nq = i % 16;
        float4 v = *reinterpret_cast<const float4*>(&Wh1[(size_t)k * 64 + nq * 4]);
        sW[k * SAPAD + nq * 4 + 0] = f2tf32(v.x);
        sW[k * SAPAD + nq * 4 + 1] = f2tf32(v.y);
        sW[k * SAPAD + nq * 4 + 2] = f2tf32(v.z);
        sW[k * SAPAD + nq * 4 + 3] = f2tf32(v.w);
    }
    __syncthreads();

    zero_acc(acc);
    mma_stage<128, 4>(sA, sW, wm, wn, g, tg, acc);
    __syncthreads();
    store_acts<4, true, true, false>(acc, bh1, sA, wm, wn, g, tg, nullptr, 0, 64, rowBase, M);
    #pragma unroll
    for (int i = tid; i < 64 * 64; i += 256) {
        int k = i / 64, j = i % 64;
        float v = (j < 40) ? Wh2[(size_t)k * 40 + j] : 0.f;
        sW[k * SAPAD + j] = f2tf32(v);
    }
    __syncthreads();

    zero_acc(acc);
    mma_stage<64, 4>(sA, sW, wm, wn, g, tg, acc);
    __syncthreads();
    store_acts<4, false, false, true>(acc, bh2, nullptr, wm, wn, g, tg, out, 40, 40, rowBase, M);
}

// ---------------- launch ----------------
extern "C" void kernel_launch(void* const* d_in, const int* in_sizes, int n_in,
                              void* d_out, int out_size) {
    const float* input_feat = (const float*)d_in[0];
    const int*   src = (const int*)d_in[1];
    const int*   dst = (const int*)d_in[2];
    const float* W1  = (const float*)d_in[3];
    const float* b1  = (const float*)d_in[4];
    const float* W2  = (const float*)d_in[5];
    const float* b2  = (const float*)d_in[6];
    const float* Wh1 = (const float*)d_in[7];
    const float* bh1 = (const float*)d_in[8];
    const float* Wh2 = (const float*)d_in[9];
    const float* bh2 = (const float*)d_in[10];

    int n = in_sizes[0] / 64;
    int e = in_sizes[1];
    if (n > NMAX) n = NMAX;
    if (e > EMAX) e = EMAX;

    float* outp = (float*)d_out;

    uint4 *h0, *hA, *hB, *hC;
    float4 *f32out, *hl_scratch;
    cudaGetSymbolAddress((void**)&h0, g_h0);
    cudaGetSymbolAddress((void**)&hA, g_hA);
    cudaGetSymbolAddress((void**)&hB, g_hB);
    cudaGetSymbolAddress((void**)&hC, g_hC);
    cudaGetSymbolAddress((void**)&f32out, g_f32out);
    cudaGetSymbolAddress((void**)&hl_scratch, g_hlast_scratch);

    float* hlast = (out_size >= n * 168) ? (outp + (size_t)n * 40) : (float*)hl_scratch;

    int nb = (n + 255) / 256;
    int eb = (e + 255) / 256;
    int ntiles = (n + 1023) / 1024;

    k_zero_deg<<<nb, 256>>>(n);
    k_degrees<<<eb, 256>>>(src, dst, e);
    k_norms_tilesum<<<ntiles, 1024>>>(n);
    k_scan_partials<<<1, 128>>>(ntiles);
    k_apply_scan<<<ntiles, 1024>>>(n);
    k_hist_scan<<<1, 256>>>();
    k_perm<<<nb, 256>>>(n);
    k_fill<<<eb, 256>>>(src, dst, e);

    // fp32 input -> fp16 rows
    int nch = n * 8;
    k_to_half<<<(nch + 255) / 256, 256>>>((const float4*)input_feat, h0, nch);

    // grid-stride persistent-shape prop (degree-sorted node order), 6 blocks/SM
    int dev = 0, smCount = 148;
    cudaGetDevice(&dev);
    cudaDeviceGetAttribute(&smCount, cudaDevAttrMultiProcessorCount, dev);
    int pbMax = (n + 31) / 32;
    int pb = smCount * 6;
    if (pb > pbMax) pb = pbMax;

    // gnn1: f0 = h0; ping-pong hA/hB, ends in hB
    const uint4* f = h0;
    for (int s = 0; s < 10; s++) {
        uint4* o = (s % 2 == 0) ? hA : hB;
        k_prop_h<false><<<pb, 256>>>(f, h0, o, n);
        f = o;
    }
    // gnn2: f0 = hB; steps 0..8 ping-pong hA/hC; final step writes fp32
    const uint4* f02 = f;   // hB
    for (int s = 0; s < 9; s++) {
        uint4* o = (s % 2 == 0) ? hA : hC;
        k_prop_h<false><<<pb, 256>>>(f, f02, o, n);
        f = o;
    }
    k_prop_h<true><<<pb, 256>>>(f, f02, f32out, n);   // step 20 -> fp32 MLP input

    // fused MLP (fp32 input, unchanged)
    const int MLP_SMEM = 2 * 128 * SAPAD * 4;
    cudaFuncSetAttribute(k_mlp, cudaFuncAttributeMaxDynamicSharedMemorySize, MLP_SMEM);
    int gridM = (n + 127) / 128;
    k_mlp<<<gridM, 256, MLP_SMEM>>>((const float*)f32out, W1, b1, W2, b2,
                                    Wh1, bh1, Wh2, bh2, hlast, outp, n);
}

// round 15
// speedup vs baseline: 1.0932x; 1.0297x over previous
#include <cuda_runtime.h>
#include <cuda_fp16.h>
#include <math.h>
#include <stdint.h>

#define NMAX 100000
#define EMAX 1000000
#define SAPAD 132

// ---------------- half2 <-> u32 bit casts ----------------
__device__ __forceinline__ uint32_t h2_bits(__half2 h) {
    return *reinterpret_cast<uint32_t*>(&h);
}
__device__ __forceinline__ __half2 bits_h2(uint32_t u) {
    return *reinterpret_cast<__half2*>(&u);
}

// ---------------- scratch (static device globals) ----------------
__device__ uint4  g_h0[(size_t)NMAX * 8];
__device__ uint4  g_hA[(size_t)NMAX * 8];
__device__ uint4  g_hB[(size_t)NMAX * 8];
__device__ uint4  g_hC[(size_t)NMAX * 8];
__device__ float4 g_f32out[(size_t)NMAX * 16];
__device__ float4 g_hlast_scratch[(size_t)NMAX * 32];
__device__ int    g_deg_out[NMAX];
__device__ int    g_deg_in[NMAX];
__device__ float  g_snorm[NMAX];
__device__ float  g_dnorm[NMAX];
__device__ int    g_rowptr[NMAX + 1];
__device__ int    g_cursor[NMAX];
__device__ int    g_partials[128];
__device__ int    g_dhist[256];
__device__ int    g_dcur[256];
__device__ int    g_perm[NMAX];
__device__ int2   g_edges[EMAX];   // .x = src, .y = bits of 0.9*snorm[src]*dnorm[dst]

// ---------------- graph preprocessing (5 launches total) ----------------
__global__ void k_zero_deg(int n) {                                        // launch 0
    int i = blockIdx.x * blockDim.x + threadIdx.x;
    if (i < n) { g_deg_out[i] = 0; g_deg_in[i] = 0; }
    if (i < 256) g_dhist[i] = 0;
}

__global__ void k_degrees(const int* __restrict__ src, const int* __restrict__ dst, int e) { // launch 1
    int i = blockIdx.x * blockDim.x + threadIdx.x;
    if (i < e) {
        atomicAdd(&g_deg_out[src[i]], 1);
        atomicAdd(&g_deg_in[dst[i]], 1);
    }
}

__global__ void k_norms_tilesum(int n) {                                   // launch 2
    int idx = blockIdx.x * 1024 + threadIdx.x;
    int din = 0;
    if (idx < n) {
        int dout = g_deg_out[idx];
        g_snorm[idx] = (dout > 0) ? rsqrtf((float)dout) : 0.f;
        din = g_deg_in[idx];
        g_dnorm[idx] = (din > 0) ? rsqrtf((float)din) : 0.f;
        atomicAdd(&g_dhist[min(din, 255)], 1);
    }
    int v = din;
    #pragma unroll
    for (int o = 16; o; o >>= 1) v += __shfl_down_sync(0xffffffffu, v, o);
    __shared__ int sm[32];
    if ((threadIdx.x & 31) == 0) sm[threadIdx.x >> 5] = v;
    __syncthreads();
    if (threadIdx.x < 32) {
        int s = sm[threadIdx.x];
        #pragma unroll
        for (int o = 16; o; o >>= 1) s += __shfl_down_sync(0xffffffffu, s, o);
        if (threadIdx.x == 0) g_partials[blockIdx.x] = s;
    }
}

// launch 3: per-tile deg_in scan (each block redundantly scans tile partials)
// + block 0 scans the 256-entry degree histogram. ALL barriers unconditional.
__global__ void k_apply_scan(int n, int ntiles) {
    int t = threadIdx.x;
    int tile = blockIdx.x;
    int lane = t & 31, w = t >> 5;

    // Phase A: redundant scan of tile partials (values only in t<128; others 0)
    __shared__ int wsA[32];
    __shared__ int tileOff;
    int pv = (t < 128 && t < ntiles) ? g_partials[t] : 0;
    int xa = pv;
    #pragma unroll
    for (int o = 1; o < 32; o <<= 1) {
        int y = __shfl_up_sync(0xffffffffu, xa, o);
        if (lane >= o) xa += y;
    }
    if (lane == 31) wsA[w] = xa;
    __syncthreads();
    if (t < 32) {
        int y = wsA[t];
        #pragma unroll
        for (int o = 1; o < 32; o <<= 1) {
            int z = __shfl_up_sync(0xffffffffu, y, o);
            if (lane >= o) y += z;
        }
        wsA[t] = y;
    }
    __syncthreads();
    if (t == tile) {   // tile < ntiles <= 98 < 1024
        int winc = (w > 0) ? wsA[w - 1] : 0;
        tileOff = xa - pv + winc;   // exclusive prefix of tile partials
    }
    __syncthreads();

    // Phase B: per-tile inclusive scan of deg_in
    int idx = tile * 1024 + t;
    int v = (idx < n) ? g_deg_in[idx] : 0;
    int x = v;
    #pragma unroll
    for (int o = 1; o < 32; o <<= 1) {
        int y = __shfl_up_sync(0xffffffffu, x, o);
        if (lane >= o) x += y;
    }
    __shared__ int wsB[32];
    if (lane == 31) wsB[w] = x;
    __syncthreads();
    if (t < 32) {
        int y = wsB[t];
        #pragma unroll
        for (int o = 1; o < 32; o <<= 1) {
            int z = __shfl_up_sync(0xffffffffu, y, o);
            if (lane >= o) y += z;
        }
        wsB[t] = y;
    }
    __syncthreads();
    int winc = (w > 0) ? wsB[w - 1] : 0;
    int inc = x + winc + tileOff;
    if (idx < n) {
        g_rowptr[idx + 1] = inc;
        g_cursor[idx] = inc - v;
    }
    if (idx == 0) g_rowptr[0] = 0;

    // Phase C: block 0 scans the 256-entry degree histogram -> g_dcur
    if (blockIdx.x == 0) {
        __shared__ int wsC[32];
        int hv = (t < 256) ? g_dhist[t] : 0;
        int xc = hv;
        #pragma unroll
        for (int o = 1; o < 32; o <<= 1) {
            int y = __shfl_up_sync(0xffffffffu, xc, o);
            if (lane >= o) xc += y;
        }
        if (lane == 31) wsC[w] = xc;
        __syncthreads();
        if (t < 32) {
            int y = wsC[t];
            #pragma unroll
            for (int o = 1; o < 32; o <<= 1) {
                int z = __shfl_up_sync(0xffffffffu, y, o);
                if (lane >= o) y += z;
            }
            wsC[t] = y;
        }
        __syncthreads();
        if (t < 256) {
            int wc = (w > 0) ? wsC[w - 1] : 0;
            g_dcur[t] = xc - hv + wc;
        }
    }
}

// launch 4: perm scatter + edge fill + fp32->fp16 convert (3 independent grid-stride loops)
__global__ void k_finalize(const int* __restrict__ src, const int* __restrict__ dst,
                           const float4* __restrict__ in32, int n, int e) {
    int tid0 = blockIdx.x * 256 + threadIdx.x;
    int gs = gridDim.x * 256;

    for (int i = tid0; i < n; i += gs) {               // perm scatter
        int d = min(g_deg_in[i], 255);
        int pos = atomicAdd(&g_dcur[d], 1);
        g_perm[pos] = i;
    }
    for (int i = tid0; i < e; i += gs) {               // edge fill
        int d = dst[i];
        int s = src[i];
        int p = atomicAdd(&g_cursor[d], 1);
        int2 v;
        v.x = s;
        v.y = __float_as_int(0.9f * g_snorm[s] * g_dnorm[d]);
        g_edges[p] = v;
    }
    int nch = n * 8;
    for (int i = tid0; i < nch; i += gs) {             // fp32 -> fp16 rows
        float4 x = __ldg(&in32[2 * i]);
        float4 y = __ldg(&in32[2 * i + 1]);
        uint4 o;
        o.x = h2_bits(__float22half2_rn(make_float2(x.x, x.y)));
        o.y = h2_bits(__float22half2_rn(make_float2(x.z, x.w)));
        o.z = h2_bits(__float22half2_rn(make_float2(y.x, y.y)));
        o.w = h2_bits(__float22half2_rn(make_float2(y.z, y.w)));
        g_h0[i] = o;
    }
}

// ---------------- APPNP propagation: fp16 rows, 8 lanes/node, degree-sorted order ----------------
#define ACC8(W, V) { \
    float2 _t0 = __half22float2(bits_h2((V).x)); \
    float2 _t1 = __half22float2(bits_h2((V).y)); \
    float2 _t2 = __half22float2(bits_h2((V).z)); \
    float2 _t3 = __half22float2(bits_h2((V).w)); \
    a0 = fmaf(W, _t0.x, a0); a1 = fmaf(W, _t0.y, a1); \
    a2 = fmaf(W, _t1.x, a2); a3 = fmaf(W, _t1.y, a3); \
    a4 = fmaf(W, _t2.x, a4); a5 = fmaf(W, _t2.y, a5); \
    a6 = fmaf(W, _t3.x, a6); a7 = fmaf(W, _t3.y, a7); }

template<bool OUT32>
__global__ void __launch_bounds__(256, 5) k_prop_h(
        const uint4* __restrict__ fp, const uint4* __restrict__ f0,
        void* __restrict__ fnv, int n) {
    int lane = threadIdx.x & 7;                    // 8 lanes per node
    int idx0 = blockIdx.x * 32 + (threadIdx.x >> 3);
    int stride = gridDim.x * 32;

    for (int i = idx0; i < n; i += stride) {
        int node = __ldg(&g_perm[i]);              // degree-sorted order
        int beg = __ldg(&g_rowptr[node]);
        int end = __ldg(&g_rowptr[node + 1]);

        float a0 = 0.f, a1 = 0.f, a2 = 0.f, a3 = 0.f;
        float a4 = 0.f, a5 = 0.f, a6 = 0.f, a7 = 0.f;

        int e = beg;
        for (; e + 4 <= end; e += 4) {
            int2 e0 = __ldg(&g_edges[e + 0]);
            int2 e1 = __ldg(&g_edges[e + 1]);
            int2 e2 = __ldg(&g_edges[e + 2]);
            int2 e3 = __ldg(&g_edges[e + 3]);
            uint4 v0 = __ldg(&fp[(size_t)e0.x * 8 + lane]);
            uint4 v1 = __ldg(&fp[(size_t)e1.x * 8 + lane]);
            uint4 v2 = __ldg(&fp[(size_t)e2.x * 8 + lane]);
            uint4 v3 = __ldg(&fp[(size_t)e3.x * 8 + lane]);
            float w0 = __int_as_float(e0.y), w1 = __int_as_float(e1.y);
            float w2 = __int_as_float(e2.y), w3 = __int_as_float(e3.y);
            ACC8(w0, v0); ACC8(w1, v1); ACC8(w2, v2); ACC8(w3, v3);
        }
        if (e + 2 <= end) {
            int2 e0 = __ldg(&g_edges[e + 0]);
            int2 e1 = __ldg(&g_edges[e + 1]);
            uint4 v0 = __ldg(&fp[(size_t)e0.x * 8 + lane]);
            uint4 v1 = __ldg(&fp[(size_t)e1.x * 8 + lane]);
            float w0 = __int_as_float(e0.y), w1 = __int_as_float(e1.y);
            ACC8(w0, v0); ACC8(w1, v1);
            e += 2;
        }
        if (e < end) {
            int2 ev = __ldg(&g_edges[e]);
            uint4 v = __ldg(&fp[(size_t)ev.x * 8 + lane]);
            float w = __int_as_float(ev.y);
            ACC8(w, v);
        }

        // + 0.1 * f0
        {
            uint4 b = __ldg(&f0[(size_t)node * 8 + lane]);
            float2 t0 = __half22float2(bits_h2(b.x));
            float2 t1 = __half22float2(bits_h2(b.y));
            float2 t2 = __half22float2(bits_h2(b.z));
            float2 t3 = __half22float2(bits_h2(b.w));
            a0 = fmaf(0.1f, t0.x, a0); a1 = fmaf(0.1f, t0.y, a1);
            a2 = fmaf(0.1f, t1.x, a2); a3 = fmaf(0.1f, t1.y, a3);
            a4 = fmaf(0.1f, t2.x, a4); a5 = fmaf(0.1f, t2.y, a5);
            a6 = fmaf(0.1f, t3.x, a6); a7 = fmaf(0.1f, t3.y, a7);
        }

        if (OUT32) {
            float4* out = (float4*)fnv;
            out[(size_t)node * 16 + lane * 2 + 0] = make_float4(a0, a1, a2, a3);
            out[(size_t)node * 16 + lane * 2 + 1] = make_float4(a4, a5, a6, a7);
        } else {
            uint4 o;
            o.x = h2_bits(__float22half2_rn(make_float2(a0, a1)));
            o.y = h2_bits(__float22half2_rn(make_float2(a2, a3)));
            o.z = h2_bits(__float22half2_rn(make_float2(a4, a5)));
            o.w = h2_bits(__float22half2_rn(make_float2(a6, a7)));
            ((uint4*)fnv)[(size_t)node * 8 + lane] = o;
        }
    }
}

// ---------------- fused tf32 MLP (unchanged) ----------------
__device__ __forceinline__ uint32_t f2tf32(float v) {
    uint32_t u;
    asm("cvt.rna.tf32.f32 %0, %1;" : "=r"(u) : "f"(v));
    return u;
}

template<int K, int NF>
__device__ __forceinline__ void mma_stage(
        const uint32_t* __restrict__ sA, const uint32_t* __restrict__ sW,
        int wm, int wn, int g, int tg, float (&acc)[2][8][4]) {
    #pragma unroll
    for (int kk = 0; kk < K; kk += 8) {
        uint32_t afr[2][4];
        #pragma unroll
        for (int mf = 0; mf < 2; mf++) {
            int mr = wm * 32 + mf * 16 + g;
            afr[mf][0] = sA[(kk + tg    ) * SAPAD + mr    ];
            afr[mf][1] = sA[(kk + tg    ) * SAPAD + mr + 8];
            afr[mf][2] = sA[(kk + tg + 4) * SAPAD + mr    ];
            afr[mf][3] = sA[(kk + tg + 4) * SAPAD + mr + 8];
        }
        #pragma unroll
        for (int nf = 0; nf < NF; nf++) {
            int nr = wn * NF * 8 + nf * 8 + g;
            uint32_t b0 = sW[(kk + tg    ) * SAPAD + nr];
            uint32_t b1 = sW[(kk + tg + 4) * SAPAD + nr];
            #pragma unroll
            for (int mf = 0; mf < 2; mf++) {
                asm volatile(
                    "mma.sync.aligned.m16n8k8.row.col.f32.tf32.tf32.f32 "
                    "{%0,%1,%2,%3}, {%4,%5,%6,%7}, {%8,%9}, {%0,%1,%2,%3};"
                    : "+f"(acc[mf][nf][0]), "+f"(acc[mf][nf][1]),
                      "+f"(acc[mf][nf][2]), "+f"(acc[mf][nf][3])
                    : "r"(afr[mf][0]), "r"(afr[mf][1]), "r"(afr[mf][2]), "r"(afr[mf][3]),
                      "r"(b0), "r"(b1));
            }
        }
    }
}

__device__ __forceinline__ void zero_acc(float (&acc)[2][8][4]) {
    #pragma unroll
    for (int i = 0; i < 2; i++)
        #pragma unroll
        for (int j = 0; j < 8; j++)
            #pragma unroll
            for (int r = 0; r < 4; r++) acc[i][j][r] = 0.f;
}

template<int NF, bool RELU, bool TO_SA, bool TO_GM>
__device__ __forceinline__ void store_acts(
        float (&acc)[2][8][4], const float* __restrict__ bias,
        uint32_t* __restrict__ sA, int wm, int wn, int g, int tg,
        float* __restrict__ gm_out, int gm_cols, int col_limit,
        int rowBase, int M) {
    #pragma unroll
    for (int mf = 0; mf < 2; mf++) {
        int r0 = wm * 32 + mf * 16 + g, r1 = r0 + 8;
        #pragma unroll
        for (int nf = 0; nf < NF; nf++) {
            int c0 = wn * NF * 8 + nf * 8 + tg * 2, c1 = c0 + 1;
            float bv0 = (c0 < col_limit) ? bias[c0] : 0.f;
            float bv1 = (c1 < col_limit) ? bias[c1] : 0.f;
            float v00 = acc[mf][nf][0] + bv0;
            float v01 = acc[mf][nf][1] + bv1;
            float v10 = acc[mf][nf][2] + bv0;
            float v11 = acc[mf][nf][3] + bv1;
            if (RELU) {
                v00 = fmaxf(v00, 0.f); v01 = fmaxf(v01, 0.f);
                v10 = fmaxf(v10, 0.f); v11 = fmaxf(v11, 0.f);
            }
            if (TO_SA) {
                sA[c0 * SAPAD + r0] = f2tf32(v00);
                sA[c1 * SAPAD + r0] = f2tf32(v01);
                sA[c0 * SAPAD + r1] = f2tf32(v10);
                sA[c1 * SAPAD + r1] = f2tf32(v11);
            }
            if (TO_GM) {
                int gr0 = rowBase + r0, gr1 = rowBase + r1;
                if (gr0 < M) {
                    if (c0 < col_limit) gm_out[(size_t)gr0 * gm_cols + c0] = v00;
                    if (c1 < col_limit) gm_out[(size_t)gr0 * gm_cols + c1] = v01;
                }
                if (gr1 < M) {
                    if (c0 < col_limit) gm_out[(size_t)gr1 * gm_cols + c0] = v10;
                    if (c1 < col_limit) gm_out[(size_t)gr1 * gm_cols + c1] = v11;
                }
            }
        }
    }
}

__global__ void __launch_bounds__(256) k_mlp(
        const float* __restrict__ X,
        const float* __restrict__ W1,  const float* __restrict__ b1,
        const float* __restrict__ W2,  const float* __restrict__ b2,
        const float* __restrict__ Wh1, const float* __restrict__ bh1,
        const float* __restrict__ Wh2, const float* __restrict__ bh2,
        float* __restrict__ hlast, float* __restrict__ out, int M) {
    extern __shared__ uint32_t sh[];
    uint32_t* sA = sh;
    uint32_t* sW = sh + 128 * SAPAD;

    int tid = threadIdx.x;
    int wid = tid >> 5, lane = tid & 31;
    int g = lane >> 2, tg = lane & 3;
    int wm = wid & 3, wn = wid >> 2;
    int rowBase = blockIdx.x * 128;

    #pragma unroll
    for (int i = tid; i < 128 * 16; i += 256) {
        int m = i / 16, kq = i % 16;
        float4 v = make_float4(0.f, 0.f, 0.f, 0.f);
        int gm = rowBase + m;
        if (gm < M) v = *reinterpret_cast<const float4*>(&X[(size_t)gm * 64 + kq * 4]);
        sA[(kq * 4 + 0) * SAPAD + m] = f2tf32(v.x);
        sA[(kq * 4 + 1) * SAPAD + m] = f2tf32(v.y);
        sA[(kq * 4 + 2) * SAPAD + m] = f2tf32(v.z);
        sA[(kq * 4 + 3) * SAPAD + m] = f2tf32(v.w);
    }
    #pragma unroll
    for (int i = tid; i < 64 * 32; i += 256) {
        int k = i / 32, nq = i % 32;
        float4 v = *reinterpret_cast<const float4*>(&W1[(size_t)k * 128 + nq * 4]);
        sW[k * SAPAD + nq * 4 + 0] = f2tf32(v.x);
        sW[k * SAPAD + nq * 4 + 1] = f2tf32(v.y);
        sW[k * SAPAD + nq * 4 + 2] = f2tf32(v.z);
        sW[k * SAPAD + nq * 4 + 3] = f2tf32(v.w);
    }
    __syncthreads();

    float acc[2][8][4];

    zero_acc(acc);
    mma_stage<64, 8>(sA, sW, wm, wn, g, tg, acc);
    __syncthreads();
    store_acts<8, true, true, false>(acc, b1, sA, wm, wn, g, tg, nullptr, 0, 128, rowBase, M);
    #pragma unroll
    for (int i = tid; i < 128 * 32; i += 256) {
        int k = i / 32, nq = i % 32;
        float4 v = *reinterpret_cast<const float4*>(&W2[(size_t)k * 128 + nq * 4]);
        sW[k * SAPAD + nq * 4 + 0] = f2tf32(v.x);
        sW[k * SAPAD + nq * 4 + 1] = f2tf32(v.y);
        sW[k * SAPAD + nq * 4 + 2] = f2tf32(v.z);
        sW[k * SAPAD + nq * 4 + 3] = f2tf32(v.w);
    }
    __syncthreads();

    zero_acc(acc);
    mma_stage<128, 8>(sA, sW, wm, wn, g, tg, acc);
    __syncthreads();
    store_acts<8, false, true, true>(acc, b2, sA, wm, wn, g, tg, hlast, 128, 128, rowBase, M);
    #pragma unroll
    for (int i = tid; i < 128 * 16; i += 256) {
        int k = i / 16, nq = i % 16;
        float4 v = *reinterpret_cast<const float4*>(&Wh1[(size_t)k * 64 + nq * 4]);
        sW[k * SAPAD + nq * 4 + 0] = f2tf32(v.x);
        sW[k * SAPAD + nq * 4 + 1] = f2tf32(v.y);
        sW[k * SAPAD + nq * 4 + 2] = f2tf32(v.z);
        sW[k * SAPAD + nq * 4 + 3] = f2tf32(v.w);
    }
    __syncthreads();

    zero_acc(acc);
    mma_stage<128, 4>(sA, sW, wm, wn, g, tg, acc);
    __syncthreads();
    store_acts<4, true, true, false>(acc, bh1, sA, wm, wn, g, tg, nullptr, 0, 64, rowBase, M);
    #pragma unroll
    for (int i = tid; i < 64 * 64; i += 256) {
        int k = i / 64, j = i % 64;
        float v = (j < 40) ? Wh2[(size_t)k * 40 + j] : 0.f;
        sW[k * SAPAD + j] = f2tf32(v);
    }
    __syncthreads();

    zero_acc(acc);
    mma_stage<64, 4>(sA, sW, wm, wn, g, tg, acc);
    __syncthreads();
    store_acts<4, false, false, true>(acc, bh2, nullptr, wm, wn, g, tg, out, 40, 40, rowBase, M);
}

// ---------------- launch ----------------
extern "C" void kernel_launch(void* const* d_in, const int* in_sizes, int n_in,
                              void* d_out, int out_size) {
    const float* input_feat = (const float*)d_in[0];
    const int*   src = (const int*)d_in[1];
    const int*   dst = (const int*)d_in[2];
    const float* W1  = (const float*)d_in[3];
    const float* b1  = (const float*)d_in[4];
    const float* W2  = (const float*)d_in[5];
    const float* b2  = (const float*)d_in[6];
    const float* Wh1 = (const float*)d_in[7];
    const float* bh1 = (const float*)d_in[8];
    const float* Wh2 = (const float*)d_in[9];
    const float* bh2 = (const float*)d_in[10];

    int n = in_sizes[0] / 64;
    int e = in_sizes[1];
    if (n > NMAX) n = NMAX;
    if (e > EMAX) e = EMAX;

    float* outp = (float*)d_out;

    uint4 *h0, *hA, *hB, *hC;
    float4 *f32out, *hl_scratch;
    cudaGetSymbolAddress((void**)&h0, g_h0);
    cudaGetSymbolAddress((void**)&hA, g_hA);
    cudaGetSymbolAddress((void**)&hB, g_hB);
    cudaGetSymbolAddress((void**)&hC, g_hC);
    cudaGetSymbolAddress((void**)&f32out, g_f32out);
    cudaGetSymbolAddress((void**)&hl_scratch, g_hlast_scratch);

    float* hlast = (out_size >= n * 168) ? (outp + (size_t)n * 40) : (float*)hl_scratch;

    int nb = (n + 255) / 256;
    int eb = (e + 255) / 256;
    int ntiles = (n + 1023) / 1024;

    k_zero_deg<<<nb, 256>>>(n);
    k_degrees<<<eb, 256>>>(src, dst, e);
    k_norms_tilesum<<<ntiles, 1024>>>(n);
    k_apply_scan<<<ntiles, 1024>>>(n, ntiles);
    k_finalize<<<eb, 256>>>(src, dst, (const float4*)input_feat, n, e);

    // grid-stride persistent-shape prop (degree-sorted node order), 5 blocks/SM
    int dev = 0, smCount = 148;
    cudaGetDevice(&dev);
    cudaDeviceGetAttribute(&smCount, cudaDevAttrMultiProcessorCount, dev);
    int pbMax = (n + 31) / 32;
    int pb = smCount * 5;
    if (pb > pbMax) pb = pbMax;

    // gnn1: f0 = h0; ping-pong hA/hB, ends in hB
    const uint4* f = h0;
    for (int s = 0; s < 10; s++) {
        uint4* o = (s % 2 == 0) ? hA : hB;
        k_prop_h<false><<<pb, 256>>>(f, h0, o, n);
        f = o;
    }
    // gnn2: f0 = hB; steps 0..8 ping-pong hA/hC; final step writes fp32
    const uint4* f02 = f;   // hB
    for (int s = 0; s < 9; s++) {
        uint4* o = (s % 2 == 0) ? hA : hC;
        k_prop_h<false><<<pb, 256>>>(f, f02, o, n);
        f = o;
    }
    k_prop_h<true><<<pb, 256>>>(f, f02, f32out, n);   // step 20 -> fp32 MLP input

    // fused MLP (fp32 input, unchanged)
    const int MLP_SMEM = 2 * 128 * SAPAD * 4;
    cudaFuncSetAttribute(k_mlp, cudaFuncAttributeMaxDynamicSharedMemorySize, MLP_SMEM);
    int gridM = (n + 127) / 128;
    k_mlp<<<gridM, 256, MLP_SMEM>>>((const float*)f32out, W1, b1, W2, b2,
                                    Wh1, bh1, Wh2, bh2, hlast, outp, n);
}